// round 16
// baseline (speedup 1.0000x reference)
#include <cuda_runtime.h>
#include <math.h>
#include <stdint.h>

#define B_     4096
#define D_     512
#define H_     512
#define V_     128
#define MAXLEN 100
#define TH3    1536   // 3*H

// ------------------------- persistent device scratch -------------------------
__device__ float g_h0[2][B_ * H_];
__device__ float g_h1[2][B_ * H_];
__device__ float g_zc0p[B_ * TH3];        // z @ Wih0[:,H:]^T + bih0 (gate-interleaved)
__device__ float g_T0p[V_ * TH3];         // emb @ Wih0[:,:H]^T (gate-interleaved)
__device__ float g_Whh0p[TH3 * H_];       // permuted: row j*3+g = Whh0[g*H+j]
__device__ float g_Wih1p[TH3 * H_];
__device__ float g_Whh1p[TH3 * H_];
__device__ float g_Wih0ep[TH3 * H_];
__device__ float g_Wih0zp[TH3 * H_];
__device__ float g_bhh0p[TH3];
__device__ float g_bi1p[TH3];
__device__ float g_bh1p[TH3];
__device__ float g_bih0p[TH3];
__device__ float g_outWt[H_ * V_];
__device__ float g_gh[B_ * TH3];          // layer1 hidden-GEMM scratch
__device__ int   g_w[B_];
__device__ int   g_eos[B_];

// --------- accurate, fast-math-immune exp / sigmoid / tanh (identical to R3 pass) ---------
__device__ __forceinline__ float exp_acc(float x) {
    x = fminf(fmaxf(x, -87.0f), 88.0f);
    float k = rintf(x * 1.4426950408889634f);
    float f = fmaf(k, -0.693359375f, x);
    f = fmaf(k, 2.12194440e-4f, f);
    float z = f * f;
    float p = 1.9875691500e-4f;
    p = fmaf(p, f, 1.3981999507e-3f);
    p = fmaf(p, f, 8.3334519073e-3f);
    p = fmaf(p, f, 4.1665795894e-2f);
    p = fmaf(p, f, 1.6666665459e-1f);
    p = fmaf(p, f, 5.0000001201e-1f);
    float y = fmaf(p, z, f) + 1.0f;
    return __int_as_float(__float_as_int(y) + (((int)k) << 23));
}
__device__ __forceinline__ float sigmoidf_(float x) { return 1.0f / (1.0f + exp_acc(-x)); }
__device__ __forceinline__ float tanhf_(float x) {
    float e = exp_acc(2.0f * x);
    return (e - 1.0f) / (e + 1.0f);
}

// ------------------------- init: weight permutation -------------------------
__global__ void permute_kernel(const float* __restrict__ Wih0,
                               const float* __restrict__ Whh0,
                               const float* __restrict__ Wih1,
                               const float* __restrict__ Whh1,
                               const float* __restrict__ bih0,
                               const float* __restrict__ bhh0,
                               const float* __restrict__ bih1,
                               const float* __restrict__ bhh1,
                               const float* __restrict__ outW) {
    int idx = blockIdx.x * blockDim.x + threadIdx.x;
    if (idx < TH3 * H_) {
        int c = idx / H_;
        int k = idx - c * H_;
        int j = c / 3, g = c - 3 * (c / 3);
        int src = g * H_ + j;
        g_Whh0p[idx]  = Whh0[src * H_ + k];
        g_Wih1p[idx]  = Wih1[src * H_ + k];
        g_Whh1p[idx]  = Whh1[src * H_ + k];
        g_Wih0ep[idx] = Wih0[src * (H_ + D_) + k];
        g_Wih0zp[idx] = Wih0[src * (H_ + D_) + H_ + k];
        if (k == 0) {
            g_bhh0p[c] = bhh0[src];
            g_bi1p[c]  = bih1[src];
            g_bh1p[c]  = bhh1[src];
            g_bih0p[c] = bih0[src];
        }
    }
    if (idx < H_ * V_) {
        int k = idx / V_, v = idx - k * V_;
        g_outWt[idx] = outW[v * H_ + k];
    }
}

__global__ void init_state_kernel(float* __restrict__ xout, float* __restrict__ endp) {
    int b = blockIdx.x * blockDim.x + threadIdx.x;
    if (b < B_) {
        g_w[b]   = 1;
        g_eos[b] = 0;
        if (endp) endp[b] = (float)MAXLEN;
        xout[b * MAXLEN] = 1.0f;
    }
}

#define ASTR 68
#define BSTR 50
#define BSTR2 68

// ------------------------- init GEMMs: 128 threads, 64x64 tile, 8x4/thread (R14) --------
__global__ void __launch_bounds__(128) gemm_init_k(const float* __restrict__ A,
                                                   const float* __restrict__ Wext,
                                                   const float* __restrict__ biasext,
                                                   int mode) {
    const float* W;
    const float* bias;
    float* C;
    float* C2 = nullptr;
    int N;
    if (mode == 0)      { W = Wext;      bias = biasext;  C = g_h0[0]; C2 = g_h1[0]; N = H_;  }
    else if (mode == 1) { W = g_Wih0zp;  bias = g_bih0p;  C = g_zc0p;  N = TH3; }
    else                { W = g_Wih0ep;  bias = nullptr;  C = g_T0p;   N = TH3; }

    __shared__ float As[16 * ASTR];
    __shared__ float Bs[16 * BSTR2];

    int tid = threadIdx.x;
    int bm = blockIdx.y * 64;
    int bn = blockIdx.x * 64;
    int rg = (tid >> 4) * 8;
    int cg = (tid & 15) * 4;

    float acc[8][4] = {};

    for (int kt = 0; kt < H_; kt += 16) {
        __syncthreads();
#pragma unroll
        for (int pp = 0; pp < 2; pp++) {
            int r = (tid >> 2) + 32 * pp, kc = (tid & 3) * 4;
            float4 v = *(const float4*)(A + (size_t)(bm + r) * H_ + kt + kc);
            As[(kc + 0) * ASTR + r] = v.x;
            As[(kc + 1) * ASTR + r] = v.y;
            As[(kc + 2) * ASTR + r] = v.z;
            As[(kc + 3) * ASTR + r] = v.w;
        }
#pragma unroll
        for (int pp = 0; pp < 2; pp++) {
            int col = (tid >> 2) + 32 * pp, kc = (tid & 3) * 4;
            float4 v = *(const float4*)(W + (size_t)(bn + col) * H_ + kt + kc);
            Bs[(kc + 0) * BSTR2 + col] = v.x;
            Bs[(kc + 1) * BSTR2 + col] = v.y;
            Bs[(kc + 2) * BSTR2 + col] = v.z;
            Bs[(kc + 3) * BSTR2 + col] = v.w;
        }
        __syncthreads();
#pragma unroll
        for (int kk = 0; kk < 16; kk++) {
            float a[8], b[4];
            *(float4*)&a[0] = *(const float4*)&As[kk * ASTR + rg];
            *(float4*)&a[4] = *(const float4*)&As[kk * ASTR + rg + 4];
            *(float4*)&b[0] = *(const float4*)&Bs[kk * BSTR2 + cg];
#pragma unroll
            for (int i = 0; i < 8; i++)
#pragma unroll
                for (int j = 0; j < 4; j++) acc[i][j] += a[i] * b[j];
        }
    }
#pragma unroll
    for (int i = 0; i < 8; i++) {
        int row = bm + rg + i;
#pragma unroll
        for (int j = 0; j < 4; j++) {
            int col = bn + cg + j;
            float v = acc[i][j] + (bias ? bias[col] : 0.0f);
            C[(size_t)row * N + col] = v;
            if (C2) C2[(size_t)row * N + col] = v;
        }
    }
}

// ============================================================================
// step kernel 1 (merged): z=0 -> layer0 fused GEMM+GRU; z=1 -> layer1 gh GEMM.
// (identical to R14)
// ============================================================================
__global__ void __launch_bounds__(64) step1_k(int p) {
    __shared__ float As[16 * ASTR];
    __shared__ float Bs[16 * BSTR];
    int tid = threadIdx.x;
    int bm = blockIdx.y * 64;
    int rg = (tid >> 3) * 8;
    int cg = (tid & 7) * 6;

    if (blockIdx.z == 0) {
        // ---- layer0: gh0 GEMM + GRU epilogue ----
        const float* __restrict__ hcur  = g_h0[p ^ 1];
        float*       __restrict__ hnext = g_h0[p];
        int j0 = blockIdx.x * 16;
        int c0 = j0 * 3;

        float acc[8][6] = {};
        for (int kt = 0; kt < H_; kt += 16) {
            __syncthreads();
#pragma unroll
            for (int pp = 0; pp < 4; pp++) {
                int r = (tid >> 2) + 16 * pp, kc = (tid & 3) * 4;
                float4 v = *(const float4*)(hcur + (size_t)(bm + r) * H_ + kt + kc);
                As[(kc + 0) * ASTR + r] = v.x;
                As[(kc + 1) * ASTR + r] = v.y;
                As[(kc + 2) * ASTR + r] = v.z;
                As[(kc + 3) * ASTR + r] = v.w;
            }
#pragma unroll
            for (int s = 0; s < 3; s++) {
                int i = tid + 64 * s;
                int col = i >> 2, kc = (i & 3) * 4;
                float4 v = *(const float4*)(g_Whh0p + (size_t)(c0 + col) * H_ + kt + kc);
                Bs[(kc + 0) * BSTR + col] = v.x;
                Bs[(kc + 1) * BSTR + col] = v.y;
                Bs[(kc + 2) * BSTR + col] = v.z;
                Bs[(kc + 3) * BSTR + col] = v.w;
            }
            __syncthreads();
#pragma unroll
            for (int kk = 0; kk < 16; kk++) {
                float a[8], b[6];
                *(float4*)&a[0] = *(const float4*)&As[kk * ASTR + rg];
                *(float4*)&a[4] = *(const float4*)&As[kk * ASTR + rg + 4];
                *(float2*)&b[0] = *(const float2*)&Bs[kk * BSTR + cg];
                *(float2*)&b[2] = *(const float2*)&Bs[kk * BSTR + cg + 2];
                *(float2*)&b[4] = *(const float2*)&Bs[kk * BSTR + cg + 4];
#pragma unroll
                for (int i = 0; i < 8; i++)
#pragma unroll
                    for (int j = 0; j < 6; j++) acc[i][j] += a[i] * b[j];
            }
        }
#pragma unroll
        for (int i = 0; i < 8; i++) {
            int b = bm + rg + i;
            int wt = g_w[b];
            const float* Trow = &g_T0p[wt * TH3];
            const float* Zrow = &g_zc0p[(size_t)b * TH3];
#pragma unroll
            for (int hh = 0; hh < 2; hh++) {
                int j = j0 + (tid & 7) * 2 + hh;
                int c = j * 3;
                float gi0 = Trow[c]     + Zrow[c];
                float gi1 = Trow[c + 1] + Zrow[c + 1];
                float gi2 = Trow[c + 2] + Zrow[c + 2];
                float gh0 = acc[i][hh * 3 + 0] + g_bhh0p[c];
                float gh1 = acc[i][hh * 3 + 1] + g_bhh0p[c + 1];
                float gh2 = acc[i][hh * 3 + 2] + g_bhh0p[c + 2];
                float rgate = sigmoidf_(gi0 + gh0);
                float zgate = sigmoidf_(gi1 + gh1);
                float nn = tanhf_(gi2 + rgate * gh2);
                float hp = hcur[(size_t)b * H_ + j];
                hnext[(size_t)b * H_ + j] = (1.0f - zgate) * nn + zgate * hp;
            }
        }
    } else {
        // ---- layer1 gh: g_gh = h1 @ Whh1p^T ----
        const float* __restrict__ Amat = g_h1[p ^ 1];
        int c0 = blockIdx.x * 48;

        float acc[8][6] = {};
        for (int kt = 0; kt < H_; kt += 16) {
            __syncthreads();
#pragma unroll
            for (int pp = 0; pp < 4; pp++) {
                int r = (tid >> 2) + 16 * pp, kc = (tid & 3) * 4;
                float4 v = *(const float4*)(Amat + (size_t)(bm + r) * H_ + kt + kc);
                As[(kc + 0) * ASTR + r] = v.x;
                As[(kc + 1) * ASTR + r] = v.y;
                As[(kc + 2) * ASTR + r] = v.z;
                As[(kc + 3) * ASTR + r] = v.w;
            }
#pragma unroll
            for (int s = 0; s < 3; s++) {
                int i = tid + 64 * s;
                int col = i >> 2, kc = (i & 3) * 4;
                float4 v = *(const float4*)(g_Whh1p + (size_t)(c0 + col) * H_ + kt + kc);
                Bs[(kc + 0) * BSTR + col] = v.x;
                Bs[(kc + 1) * BSTR + col] = v.y;
                Bs[(kc + 2) * BSTR + col] = v.z;
                Bs[(kc + 3) * BSTR + col] = v.w;
            }
            __syncthreads();
#pragma unroll
            for (int kk = 0; kk < 16; kk++) {
                float a[8], b[6];
                *(float4*)&a[0] = *(const float4*)&As[kk * ASTR + rg];
                *(float4*)&a[4] = *(const float4*)&As[kk * ASTR + rg + 4];
                *(float2*)&b[0] = *(const float2*)&Bs[kk * BSTR + cg];
                *(float2*)&b[2] = *(const float2*)&Bs[kk * BSTR + cg + 2];
                *(float2*)&b[4] = *(const float2*)&Bs[kk * BSTR + cg + 4];
#pragma unroll
                for (int i = 0; i < 8; i++)
#pragma unroll
                    for (int j = 0; j < 6; j++) acc[i][j] += a[i] * b[j];
            }
        }
#pragma unroll
        for (int i = 0; i < 8; i++) {
            size_t o = (size_t)(bm + rg + i) * TH3 + c0 + cg;
            *(float2*)&g_gh[o]     = make_float2(acc[i][0], acc[i][1]);
            *(float2*)&g_gh[o + 2] = make_float2(acc[i][2], acc[i][3]);
            *(float2*)&g_gh[o + 4] = make_float2(acc[i][4], acc[i][5]);
        }
    }
}

// ============================================================================
// gi_k: gi GEMM (gi stays in registers) + layer1 GRU epilogue -> writes h1[p].
// gh tile read from g_gh (written by completed step1_k). Same per-element
// arithmetic chains as the former scratch+fuse path -> bit-identical.
// ============================================================================
__global__ void __launch_bounds__(64) gi_k(int p) {
    const float* __restrict__ Amat  = g_h0[p];       // h_l0
    const float* __restrict__ hprev = g_h1[p ^ 1];
    float*       __restrict__ hnew  = g_h1[p];

    __shared__ float As[16 * ASTR];
    __shared__ float Bs[16 * BSTR];

    int tid = threadIdx.x;
    int bm = blockIdx.y * 64;
    int j0 = blockIdx.x * 16;     // h-unit base (48 cols = 16 triples)
    int c0 = j0 * 3;
    int rg = (tid >> 3) * 8;
    int cg = (tid & 7) * 6;

    float acc[8][6] = {};

    for (int kt = 0; kt < H_; kt += 16) {
        __syncthreads();
#pragma unroll
        for (int pp = 0; pp < 4; pp++) {
            int r = (tid >> 2) + 16 * pp, kc = (tid & 3) * 4;
            float4 v = *(const float4*)(Amat + (size_t)(bm + r) * H_ + kt + kc);
            As[(kc + 0) * ASTR + r] = v.x;
            As[(kc + 1) * ASTR + r] = v.y;
            As[(kc + 2) * ASTR + r] = v.z;
            As[(kc + 3) * ASTR + r] = v.w;
        }
#pragma unroll
        for (int s = 0; s < 3; s++) {
            int i = tid + 64 * s;
            int col = i >> 2, kc = (i & 3) * 4;
            float4 v = *(const float4*)(g_Wih1p + (size_t)(c0 + col) * H_ + kt + kc);
            Bs[(kc + 0) * BSTR + col] = v.x;
            Bs[(kc + 1) * BSTR + col] = v.y;
            Bs[(kc + 2) * BSTR + col] = v.z;
            Bs[(kc + 3) * BSTR + col] = v.w;
        }
        __syncthreads();
#pragma unroll
        for (int kk = 0; kk < 16; kk++) {
            float a[8], b[6];
            *(float4*)&a[0] = *(const float4*)&As[kk * ASTR + rg];
            *(float4*)&a[4] = *(const float4*)&As[kk * ASTR + rg + 4];
            *(float2*)&b[0] = *(const float2*)&Bs[kk * BSTR + cg];
            *(float2*)&b[2] = *(const float2*)&Bs[kk * BSTR + cg + 2];
            *(float2*)&b[4] = *(const float2*)&Bs[kk * BSTR + cg + 4];
#pragma unroll
            for (int i = 0; i < 8; i++)
#pragma unroll
                for (int j = 0; j < 6; j++) acc[i][j] += a[i] * b[j];
        }
    }
    // fused layer1 GRU epilogue: gi from registers, gh tile from gmem scratch
#pragma unroll
    for (int i = 0; i < 8; i++) {
        int b = bm + rg + i;
        const float* ghrow = &g_gh[(size_t)b * TH3];
#pragma unroll
        for (int hh = 0; hh < 2; hh++) {
            int j = j0 + (tid & 7) * 2 + hh;
            int c = j * 3;
            float gi0 = acc[i][hh * 3 + 0] + g_bi1p[c];
            float gi1 = acc[i][hh * 3 + 1] + g_bi1p[c + 1];
            float gi2 = acc[i][hh * 3 + 2] + g_bi1p[c + 2];
            float gh0 = ghrow[c]     + g_bh1p[c];
            float gh1 = ghrow[c + 1] + g_bh1p[c + 1];
            float gh2 = ghrow[c + 2] + g_bh1p[c + 2];
            float rgate = sigmoidf_(gi0 + gh0);
            float zgate = sigmoidf_(gi1 + gh1);
            float nn = tanhf_(gi2 + rgate * gh2);
            float hp = hprev[(size_t)b * H_ + j];
            hnew[(size_t)b * H_ + j] = (1.0f - zgate) * nn + zgate * hp;
        }
    }
}

// ============================================================================
// logits_k: logits GEMM + argmax + token logic from h1[p] (8 rows/block).
// ============================================================================
__global__ void __launch_bounds__(256) logits_k(int p, const float* __restrict__ out_b,
                                                float* __restrict__ xout,
                                                float* __restrict__ endp, int step) {
    __shared__ float Hs[8 * H_];        // 16 KB
    __shared__ float Ls[8][129];
    int b0 = blockIdx.x * 8;
    int tid = threadIdx.x;
    const float* __restrict__ h = g_h1[p];

    // stage 8 rows of h1 into smem
    const float4* src = (const float4*)(h + (size_t)b0 * H_);
    float4* dst = (float4*)Hs;
#pragma unroll
    for (int s = 0; s < 4; s++) dst[tid + 256 * s] = src[tid + 256 * s];
    __syncthreads();

    int vt = tid & 127, half = tid >> 7;
    float acc[4];
#pragma unroll
    for (int r = 0; r < 4; r++) acc[r] = 0.0f;
    for (int k = 0; k < H_; k += 4) {
        float w0 = g_outWt[(k + 0) * V_ + vt];
        float w1 = g_outWt[(k + 1) * V_ + vt];
        float w2 = g_outWt[(k + 2) * V_ + vt];
        float w3 = g_outWt[(k + 3) * V_ + vt];
#pragma unroll
        for (int r = 0; r < 4; r++) {
            float4 hv = *(const float4*)&Hs[(half * 4 + r) * H_ + k];
            acc[r] += hv.x * w0 + hv.y * w1 + hv.z * w2 + hv.w * w3;
        }
    }
    float bb = out_b[vt];
#pragma unroll
    for (int r = 0; r < 4; r++) Ls[half * 4 + r][vt] = acc[r] + bb;
    __syncthreads();

    if (tid < 8) {
        int b = b0 + tid;
        const float* row = Ls[tid];
        float best = row[0];
        int bi = 0;
        for (int v = 1; v < V_; v++) {
            float xv = row[v];
            if (xv > best) { best = xv; bi = v; }
        }
        int eo = g_eos[b];
        xout[b * MAXLEN + step] = eo ? 0.0f : (float)bi;
        if (!eo && bi == 2) {
            if (endp) endp[b] = (float)(step + 1);
            g_eos[b] = 1;
        }
        g_w[b] = bi;
    }
}

// ------------------------- launch -------------------------
extern "C" void kernel_launch(void* const* d_in, const int* in_sizes, int n_in,
                              void* d_out, int out_size) {
    static const int want[14] = {
        B_ * D_, V_ * H_, H_ * D_, H_,
        TH3 * (H_ + D_), TH3 * H_, TH3, TH3,
        TH3 * H_, TH3 * H_, TH3, TH3,
        V_ * H_, V_
    };
    const float* in[14];
    bool used[14] = {};
    bool ok = (n_in >= 14);
    for (int i = 0; i < 14 && ok; i++) {
        int found = -1;
        for (int j = 0; j < 14; j++) {
            if (!used[j] && in_sizes[j] == want[i]) { found = j; break; }
        }
        if (found < 0) { ok = false; break; }
        used[found] = true;
        in[i] = (const float*)d_in[found];
    }
    if (!ok) {
        for (int i = 0; i < 14; i++) in[i] = (const float*)d_in[i];
    }
    const float* z     = in[0];
    const float* emb   = in[1];
    const float* lat_W = in[2];
    const float* lat_b = in[3];
    const float* out_b = in[13];

    float* xout = (float*)d_out;
    float* endp = nullptr;
    if (out_size >= B_ * MAXLEN + B_) {
        endp = xout + (out_size - B_);
    }

    permute_kernel<<<(TH3 * H_ + 255) / 256, 256>>>(in[4], in[5], in[8], in[9],
                                                    in[6], in[7], in[10], in[11], in[12]);
    init_state_kernel<<<(B_ + 255) / 256, 256>>>(xout, endp);
    gemm_init_k<<<dim3(H_ / 64, B_ / 64), 128>>>(z, lat_W, lat_b, 0);
    gemm_init_k<<<dim3(TH3 / 64, B_ / 64), 128>>>(z, nullptr, nullptr, 1);
    gemm_init_k<<<dim3(TH3 / 64, V_ / 64), 128>>>(emb, nullptr, nullptr, 2);

    for (int s = 1; s < MAXLEN; s++) {
        int p = s & 1;
        step1_k<<<dim3(32, B_ / 64, 2), 64>>>(p);   // layer0 (z=0) + layer1 gh (z=1)
        gi_k<<<dim3(H_ / 16, B_ / 64), 64>>>(p);    // layer1 gi GEMM + GRU epilogue -> h1
        logits_k<<<B_ / 8, 256>>>(p, out_b, xout, endp, s);
    }
}

// round 17
// speedup vs baseline: 1.0446x; 1.0446x over previous
#include <cuda_runtime.h>
#include <math.h>
#include <stdint.h>

#define B_     4096
#define D_     512
#define H_     512
#define V_     128
#define MAXLEN 100
#define TH3    1536   // 3*H

// ------------------------- persistent device scratch -------------------------
__device__ float g_h0[2][B_ * H_];
__device__ float g_h1[2][B_ * H_];
__device__ float g_zc0p[B_ * TH3];        // z @ Wih0[:,H:]^T + bih0 (gate-interleaved)
__device__ float g_T0p[V_ * TH3];         // emb @ Wih0[:,:H]^T (gate-interleaved)
__device__ float g_Whh0p[TH3 * H_];       // permuted: row j*3+g = Whh0[g*H+j]
__device__ float g_Wih1p[TH3 * H_];
__device__ float g_Whh1p[TH3 * H_];
__device__ float g_Wih0ep[TH3 * H_];
__device__ float g_Wih0zp[TH3 * H_];
__device__ float g_bhh0p[TH3];
__device__ float g_bi1p[TH3];
__device__ float g_bh1p[TH3];
__device__ float g_bih0p[TH3];
__device__ float g_outWt[H_ * V_];
__device__ float g_gi[B_ * TH3];          // layer1 input-GEMM scratch
__device__ float g_gh[B_ * TH3];          // layer1 hidden-GEMM scratch
__device__ int   g_w[B_];
__device__ int   g_eos[B_];

// --------- accurate, fast-math-immune exp / sigmoid / tanh (identical to R3 pass) ---------
__device__ __forceinline__ float exp_acc(float x) {
    x = fminf(fmaxf(x, -87.0f), 88.0f);
    float k = rintf(x * 1.4426950408889634f);
    float f = fmaf(k, -0.693359375f, x);
    f = fmaf(k, 2.12194440e-4f, f);
    float z = f * f;
    float p = 1.9875691500e-4f;
    p = fmaf(p, f, 1.3981999507e-3f);
    p = fmaf(p, f, 8.3334519073e-3f);
    p = fmaf(p, f, 4.1665795894e-2f);
    p = fmaf(p, f, 1.6666665459e-1f);
    p = fmaf(p, f, 5.0000001201e-1f);
    float y = fmaf(p, z, f) + 1.0f;
    return __int_as_float(__float_as_int(y) + (((int)k) << 23));
}
__device__ __forceinline__ float sigmoidf_(float x) { return 1.0f / (1.0f + exp_acc(-x)); }
__device__ __forceinline__ float tanhf_(float x) {
    float e = exp_acc(2.0f * x);
    return (e - 1.0f) / (e + 1.0f);
}

// ------------------------- init: weight permutation -------------------------
__global__ void permute_kernel(const float* __restrict__ Wih0,
                               const float* __restrict__ Whh0,
                               const float* __restrict__ Wih1,
                               const float* __restrict__ Whh1,
                               const float* __restrict__ bih0,
                               const float* __restrict__ bhh0,
                               const float* __restrict__ bih1,
                               const float* __restrict__ bhh1,
                               const float* __restrict__ outW) {
    int idx = blockIdx.x * blockDim.x + threadIdx.x;
    if (idx < TH3 * H_) {
        int c = idx / H_;
        int k = idx - c * H_;
        int j = c / 3, g = c - 3 * (c / 3);
        int src = g * H_ + j;
        g_Whh0p[idx]  = Whh0[src * H_ + k];
        g_Wih1p[idx]  = Wih1[src * H_ + k];
        g_Whh1p[idx]  = Whh1[src * H_ + k];
        g_Wih0ep[idx] = Wih0[src * (H_ + D_) + k];
        g_Wih0zp[idx] = Wih0[src * (H_ + D_) + H_ + k];
        if (k == 0) {
            g_bhh0p[c] = bhh0[src];
            g_bi1p[c]  = bih1[src];
            g_bh1p[c]  = bhh1[src];
            g_bih0p[c] = bih0[src];
        }
    }
    if (idx < H_ * V_) {
        int k = idx / V_, v = idx - k * V_;
        g_outWt[idx] = outW[v * H_ + k];
    }
}

__global__ void init_state_kernel(float* __restrict__ xout, float* __restrict__ endp) {
    int b = blockIdx.x * blockDim.x + threadIdx.x;
    if (b < B_) {
        g_w[b]   = 1;
        g_eos[b] = 0;
        if (endp) endp[b] = (float)MAXLEN;
        xout[b * MAXLEN] = 1.0f;
    }
}

#define ASTR 68
#define BSTR 50
#define BSTR2 68

// ------------------------- init GEMM mode 0 (h_init): 128 threads, 64x64 tile --------
__global__ void __launch_bounds__(128) init0_k(const float* __restrict__ z,
                                               const float* __restrict__ lat_W,
                                               const float* __restrict__ lat_b) {
    __shared__ float As[16 * ASTR];
    __shared__ float Bs[16 * BSTR2];

    int tid = threadIdx.x;
    int bm = blockIdx.y * 64;
    int bn = blockIdx.x * 64;
    int rg = (tid >> 4) * 8;
    int cg = (tid & 15) * 4;

    float acc[8][4] = {};

    for (int kt = 0; kt < H_; kt += 16) {
        __syncthreads();
#pragma unroll
        for (int pp = 0; pp < 2; pp++) {
            int r = (tid >> 2) + 32 * pp, kc = (tid & 3) * 4;
            float4 v = *(const float4*)(z + (size_t)(bm + r) * H_ + kt + kc);
            As[(kc + 0) * ASTR + r] = v.x;
            As[(kc + 1) * ASTR + r] = v.y;
            As[(kc + 2) * ASTR + r] = v.z;
            As[(kc + 3) * ASTR + r] = v.w;
        }
#pragma unroll
        for (int pp = 0; pp < 2; pp++) {
            int col = (tid >> 2) + 32 * pp, kc = (tid & 3) * 4;
            float4 v = *(const float4*)(lat_W + (size_t)(bn + col) * H_ + kt + kc);
            Bs[(kc + 0) * BSTR2 + col] = v.x;
            Bs[(kc + 1) * BSTR2 + col] = v.y;
            Bs[(kc + 2) * BSTR2 + col] = v.z;
            Bs[(kc + 3) * BSTR2 + col] = v.w;
        }
        __syncthreads();
#pragma unroll
        for (int kk = 0; kk < 16; kk++) {
            float a[8], b[4];
            *(float4*)&a[0] = *(const float4*)&As[kk * ASTR + rg];
            *(float4*)&a[4] = *(const float4*)&As[kk * ASTR + rg + 4];
            *(float4*)&b[0] = *(const float4*)&Bs[kk * BSTR2 + cg];
#pragma unroll
            for (int i = 0; i < 8; i++)
#pragma unroll
                for (int j = 0; j < 4; j++) acc[i][j] += a[i] * b[j];
        }
    }
#pragma unroll
    for (int i = 0; i < 8; i++) {
        int row = bm + rg + i;
#pragma unroll
        for (int j = 0; j < 4; j++) {
            int col = bn + cg + j;
            float v = acc[i][j] + lat_b[col];
            g_h0[0][(size_t)row * H_ + col] = v;
            g_h1[0][(size_t)row * H_ + col] = v;
        }
    }
}

// ------------------------- init GEMM modes 1+2 merged (zc0p / T0p) --------
// grid (24, 66): by<64 -> zc0p rows (A=z, bias); by>=64 -> T0p rows (A=emb, no bias).
// Same body as R14's gemm_init_k -> per-element chains bit-identical.
__global__ void __launch_bounds__(128) init12_k(const float* __restrict__ z,
                                                const float* __restrict__ emb) {
    const float* A;
    const float* W;
    const float* bias;
    float* C;
    int bm;
    if (blockIdx.y < 64) {
        A = z;   W = g_Wih0zp; bias = g_bih0p; C = g_zc0p;
        bm = blockIdx.y * 64;
    } else {
        A = emb; W = g_Wih0ep; bias = nullptr; C = g_T0p;
        bm = (blockIdx.y - 64) * 64;
    }
    int bn = blockIdx.x * 64;

    __shared__ float As[16 * ASTR];
    __shared__ float Bs[16 * BSTR2];

    int tid = threadIdx.x;
    int rg = (tid >> 4) * 8;
    int cg = (tid & 15) * 4;

    float acc[8][4] = {};

    for (int kt = 0; kt < H_; kt += 16) {
        __syncthreads();
#pragma unroll
        for (int pp = 0; pp < 2; pp++) {
            int r = (tid >> 2) + 32 * pp, kc = (tid & 3) * 4;
            float4 v = *(const float4*)(A + (size_t)(bm + r) * H_ + kt + kc);
            As[(kc + 0) * ASTR + r] = v.x;
            As[(kc + 1) * ASTR + r] = v.y;
            As[(kc + 2) * ASTR + r] = v.z;
            As[(kc + 3) * ASTR + r] = v.w;
        }
#pragma unroll
        for (int pp = 0; pp < 2; pp++) {
            int col = (tid >> 2) + 32 * pp, kc = (tid & 3) * 4;
            float4 v = *(const float4*)(W + (size_t)(bn + col) * H_ + kt + kc);
            Bs[(kc + 0) * BSTR2 + col] = v.x;
            Bs[(kc + 1) * BSTR2 + col] = v.y;
            Bs[(kc + 2) * BSTR2 + col] = v.z;
            Bs[(kc + 3) * BSTR2 + col] = v.w;
        }
        __syncthreads();
#pragma unroll
        for (int kk = 0; kk < 16; kk++) {
            float a[8], b[4];
            *(float4*)&a[0] = *(const float4*)&As[kk * ASTR + rg];
            *(float4*)&a[4] = *(const float4*)&As[kk * ASTR + rg + 4];
            *(float4*)&b[0] = *(const float4*)&Bs[kk * BSTR2 + cg];
#pragma unroll
            for (int i = 0; i < 8; i++)
#pragma unroll
                for (int j = 0; j < 4; j++) acc[i][j] += a[i] * b[j];
        }
    }
#pragma unroll
    for (int i = 0; i < 8; i++) {
        int row = bm + rg + i;
#pragma unroll
        for (int j = 0; j < 4; j++) {
            int col = bn + cg + j;
            float v = acc[i][j] + (bias ? bias[col] : 0.0f);
            C[(size_t)row * TH3 + col] = v;
        }
    }
}

// ============================================================================
// step kernel 1 (merged): z=0 -> layer0 fused GEMM+GRU; z=1 -> layer1 gh GEMM.
// (identical to R14 — the best-measured configuration)
// ============================================================================
__global__ void __launch_bounds__(64) step1_k(int p) {
    __shared__ float As[16 * ASTR];
    __shared__ float Bs[16 * BSTR];
    int tid = threadIdx.x;
    int bm = blockIdx.y * 64;
    int rg = (tid >> 3) * 8;
    int cg = (tid & 7) * 6;

    if (blockIdx.z == 0) {
        // ---- layer0: gh0 GEMM + GRU epilogue ----
        const float* __restrict__ hcur  = g_h0[p ^ 1];
        float*       __restrict__ hnext = g_h0[p];
        int j0 = blockIdx.x * 16;
        int c0 = j0 * 3;

        float acc[8][6] = {};
        for (int kt = 0; kt < H_; kt += 16) {
            __syncthreads();
#pragma unroll
            for (int pp = 0; pp < 4; pp++) {
                int r = (tid >> 2) + 16 * pp, kc = (tid & 3) * 4;
                float4 v = *(const float4*)(hcur + (size_t)(bm + r) * H_ + kt + kc);
                As[(kc + 0) * ASTR + r] = v.x;
                As[(kc + 1) * ASTR + r] = v.y;
                As[(kc + 2) * ASTR + r] = v.z;
                As[(kc + 3) * ASTR + r] = v.w;
            }
#pragma unroll
            for (int s = 0; s < 3; s++) {
                int i = tid + 64 * s;
                int col = i >> 2, kc = (i & 3) * 4;
                float4 v = *(const float4*)(g_Whh0p + (size_t)(c0 + col) * H_ + kt + kc);
                Bs[(kc + 0) * BSTR + col] = v.x;
                Bs[(kc + 1) * BSTR + col] = v.y;
                Bs[(kc + 2) * BSTR + col] = v.z;
                Bs[(kc + 3) * BSTR + col] = v.w;
            }
            __syncthreads();
#pragma unroll
            for (int kk = 0; kk < 16; kk++) {
                float a[8], b[6];
                *(float4*)&a[0] = *(const float4*)&As[kk * ASTR + rg];
                *(float4*)&a[4] = *(const float4*)&As[kk * ASTR + rg + 4];
                *(float2*)&b[0] = *(const float2*)&Bs[kk * BSTR + cg];
                *(float2*)&b[2] = *(const float2*)&Bs[kk * BSTR + cg + 2];
                *(float2*)&b[4] = *(const float2*)&Bs[kk * BSTR + cg + 4];
#pragma unroll
                for (int i = 0; i < 8; i++)
#pragma unroll
                    for (int j = 0; j < 6; j++) acc[i][j] += a[i] * b[j];
            }
        }
#pragma unroll
        for (int i = 0; i < 8; i++) {
            int b = bm + rg + i;
            int wt = g_w[b];
            const float* Trow = &g_T0p[wt * TH3];
            const float* Zrow = &g_zc0p[(size_t)b * TH3];
#pragma unroll
            for (int hh = 0; hh < 2; hh++) {
                int j = j0 + (tid & 7) * 2 + hh;
                int c = j * 3;
                float gi0 = Trow[c]     + Zrow[c];
                float gi1 = Trow[c + 1] + Zrow[c + 1];
                float gi2 = Trow[c + 2] + Zrow[c + 2];
                float gh0 = acc[i][hh * 3 + 0] + g_bhh0p[c];
                float gh1 = acc[i][hh * 3 + 1] + g_bhh0p[c + 1];
                float gh2 = acc[i][hh * 3 + 2] + g_bhh0p[c + 2];
                float rgate = sigmoidf_(gi0 + gh0);
                float zgate = sigmoidf_(gi1 + gh1);
                float nn = tanhf_(gi2 + rgate * gh2);
                float hp = hcur[(size_t)b * H_ + j];
                hnext[(size_t)b * H_ + j] = (1.0f - zgate) * nn + zgate * hp;
            }
        }
    } else {
        // ---- layer1 gh: g_gh = h1 @ Whh1p^T ----
        const float* __restrict__ Amat = g_h1[p ^ 1];
        int c0 = blockIdx.x * 48;

        float acc[8][6] = {};
        for (int kt = 0; kt < H_; kt += 16) {
            __syncthreads();
#pragma unroll
            for (int pp = 0; pp < 4; pp++) {
                int r = (tid >> 2) + 16 * pp, kc = (tid & 3) * 4;
                float4 v = *(const float4*)(Amat + (size_t)(bm + r) * H_ + kt + kc);
                As[(kc + 0) * ASTR + r] = v.x;
                As[(kc + 1) * ASTR + r] = v.y;
                As[(kc + 2) * ASTR + r] = v.z;
                As[(kc + 3) * ASTR + r] = v.w;
            }
#pragma unroll
            for (int s = 0; s < 3; s++) {
                int i = tid + 64 * s;
                int col = i >> 2, kc = (i & 3) * 4;
                float4 v = *(const float4*)(g_Whh1p + (size_t)(c0 + col) * H_ + kt + kc);
                Bs[(kc + 0) * BSTR + col] = v.x;
                Bs[(kc + 1) * BSTR + col] = v.y;
                Bs[(kc + 2) * BSTR + col] = v.z;
                Bs[(kc + 3) * BSTR + col] = v.w;
            }
            __syncthreads();
#pragma unroll
            for (int kk = 0; kk < 16; kk++) {
                float a[8], b[6];
                *(float4*)&a[0] = *(const float4*)&As[kk * ASTR + rg];
                *(float4*)&a[4] = *(const float4*)&As[kk * ASTR + rg + 4];
                *(float2*)&b[0] = *(const float2*)&Bs[kk * BSTR + cg];
                *(float2*)&b[2] = *(const float2*)&Bs[kk * BSTR + cg + 2];
                *(float2*)&b[4] = *(const float2*)&Bs[kk * BSTR + cg + 4];
#pragma unroll
                for (int i = 0; i < 8; i++)
#pragma unroll
                    for (int j = 0; j < 6; j++) acc[i][j] += a[i] * b[j];
            }
        }
#pragma unroll
        for (int i = 0; i < 8; i++) {
            size_t o = (size_t)(bm + rg + i) * TH3 + c0 + cg;
            *(float2*)&g_gh[o]     = make_float2(acc[i][0], acc[i][1]);
            *(float2*)&g_gh[o + 2] = make_float2(acc[i][2], acc[i][3]);
            *(float2*)&g_gh[o + 4] = make_float2(acc[i][4], acc[i][5]);
        }
    }
}

// ============================================================================
// step kernel 2: gi = h_l0 @ Wih1p^T into scratch (identical to R14)
// ============================================================================
__global__ void __launch_bounds__(64) gi_k(int p) {
    const float* __restrict__ Amat = g_h0[p];

    __shared__ float As[16 * ASTR];
    __shared__ float Bs[16 * BSTR];

    int tid = threadIdx.x;
    int bm = blockIdx.y * 64;
    int c0 = blockIdx.x * 48;
    int rg = (tid >> 3) * 8;
    int cg = (tid & 7) * 6;

    float acc[8][6] = {};

    for (int kt = 0; kt < H_; kt += 16) {
        __syncthreads();
#pragma unroll
        for (int pp = 0; pp < 4; pp++) {
            int r = (tid >> 2) + 16 * pp, kc = (tid & 3) * 4;
            float4 v = *(const float4*)(Amat + (size_t)(bm + r) * H_ + kt + kc);
            As[(kc + 0) * ASTR + r] = v.x;
            As[(kc + 1) * ASTR + r] = v.y;
            As[(kc + 2) * ASTR + r] = v.z;
            As[(kc + 3) * ASTR + r] = v.w;
        }
#pragma unroll
        for (int s = 0; s < 3; s++) {
            int i = tid + 64 * s;
            int col = i >> 2, kc = (i & 3) * 4;
            float4 v = *(const float4*)(g_Wih1p + (size_t)(c0 + col) * H_ + kt + kc);
            Bs[(kc + 0) * BSTR + col] = v.x;
            Bs[(kc + 1) * BSTR + col] = v.y;
            Bs[(kc + 2) * BSTR + col] = v.z;
            Bs[(kc + 3) * BSTR + col] = v.w;
        }
        __syncthreads();
#pragma unroll
        for (int kk = 0; kk < 16; kk++) {
            float a[8], b[6];
            *(float4*)&a[0] = *(const float4*)&As[kk * ASTR + rg];
            *(float4*)&a[4] = *(const float4*)&As[kk * ASTR + rg + 4];
            *(float2*)&b[0] = *(const float2*)&Bs[kk * BSTR + cg];
            *(float2*)&b[2] = *(const float2*)&Bs[kk * BSTR + cg + 2];
            *(float2*)&b[4] = *(const float2*)&Bs[kk * BSTR + cg + 4];
#pragma unroll
            for (int i = 0; i < 8; i++)
#pragma unroll
                for (int j = 0; j < 6; j++) acc[i][j] += a[i] * b[j];
        }
    }
#pragma unroll
    for (int i = 0; i < 8; i++) {
        size_t o = (size_t)(bm + rg + i) * TH3 + c0 + cg;
        *(float2*)&g_gi[o]     = make_float2(acc[i][0], acc[i][1]);
        *(float2*)&g_gi[o + 2] = make_float2(acc[i][2], acc[i][3]);
        *(float2*)&g_gi[o + 4] = make_float2(acc[i][4], acc[i][5]);
    }
}

// ============================================================================
// fuse_k: layer1 GRU epilogue + logits GEMM + argmax + token logic (identical to R14).
// ============================================================================
__global__ void __launch_bounds__(256) fuse_k(int p, const float* __restrict__ out_b,
                                              float* __restrict__ xout,
                                              float* __restrict__ endp, int step) {
    __shared__ float Hs[8 * H_];        // 16 KB
    __shared__ float Ls[8][129];
    int b0 = blockIdx.x * 8;
    int tid = threadIdx.x;
    const float* __restrict__ hprev = g_h1[p ^ 1];
    float*       __restrict__ hnew  = g_h1[p];

#pragma unroll
    for (int s = 0; s < 16; s++) {
        int idx = tid + 256 * s;
        int row = idx >> 9, j = idx & 511;
        int b = b0 + row;
        int c = j * 3;
        size_t o = (size_t)b * TH3 + c;
        float gi0 = g_gi[o]     + g_bi1p[c];
        float gi1 = g_gi[o + 1] + g_bi1p[c + 1];
        float gi2 = g_gi[o + 2] + g_bi1p[c + 2];
        float gh0 = g_gh[o]     + g_bh1p[c];
        float gh1 = g_gh[o + 1] + g_bh1p[c + 1];
        float gh2 = g_gh[o + 2] + g_bh1p[c + 2];
        float rgate = sigmoidf_(gi0 + gh0);
        float zgate = sigmoidf_(gi1 + gh1);
        float nn = tanhf_(gi2 + rgate * gh2);
        float hp = hprev[(size_t)b * H_ + j];
        float hv = (1.0f - zgate) * nn + zgate * hp;
        Hs[row * H_ + j] = hv;
        hnew[(size_t)b * H_ + j] = hv;
    }
    __syncthreads();

    int vt = tid & 127, half = tid >> 7;
    float acc[4];
#pragma unroll
    for (int r = 0; r < 4; r++) acc[r] = 0.0f;
    for (int k = 0; k < H_; k += 4) {
        float w0 = g_outWt[(k + 0) * V_ + vt];
        float w1 = g_outWt[(k + 1) * V_ + vt];
        float w2 = g_outWt[(k + 2) * V_ + vt];
        float w3 = g_outWt[(k + 3) * V_ + vt];
#pragma unroll
        for (int r = 0; r < 4; r++) {
            float4 hv = *(const float4*)&Hs[(half * 4 + r) * H_ + k];
            acc[r] += hv.x * w0 + hv.y * w1 + hv.z * w2 + hv.w * w3;
        }
    }
    float bb = out_b[vt];
#pragma unroll
    for (int r = 0; r < 4; r++) Ls[half * 4 + r][vt] = acc[r] + bb;
    __syncthreads();

    if (tid < 8) {
        int b = b0 + tid;
        const float* row = Ls[tid];
        float best = row[0];
        int bi = 0;
        for (int v = 1; v < V_; v++) {
            float xv = row[v];
            if (xv > best) { best = xv; bi = v; }
        }
        int eo = g_eos[b];
        xout[b * MAXLEN + step] = eo ? 0.0f : (float)bi;
        if (!eo && bi == 2) {
            if (endp) endp[b] = (float)(step + 1);
            g_eos[b] = 1;
        }
        g_w[b] = bi;
    }
}

// ------------------------- launch -------------------------
extern "C" void kernel_launch(void* const* d_in, const int* in_sizes, int n_in,
                              void* d_out, int out_size) {
    static const int want[14] = {
        B_ * D_, V_ * H_, H_ * D_, H_,
        TH3 * (H_ + D_), TH3 * H_, TH3, TH3,
        TH3 * H_, TH3 * H_, TH3, TH3,
        V_ * H_, V_
    };
    const float* in[14];
    bool used[14] = {};
    bool ok = (n_in >= 14);
    for (int i = 0; i < 14 && ok; i++) {
        int found = -1;
        for (int j = 0; j < 14; j++) {
            if (!used[j] && in_sizes[j] == want[i]) { found = j; break; }
        }
        if (found < 0) { ok = false; break; }
        used[found] = true;
        in[i] = (const float*)d_in[found];
    }
    if (!ok) {
        for (int i = 0; i < 14; i++) in[i] = (const float*)d_in[i];
    }
    const float* z     = in[0];
    const float* emb   = in[1];
    const float* lat_W = in[2];
    const float* lat_b = in[3];
    const float* out_b = in[13];

    float* xout = (float*)d_out;
    float* endp = nullptr;
    if (out_size >= B_ * MAXLEN + B_) {
        endp = xout + (out_size - B_);
    }

    permute_kernel<<<(TH3 * H_ + 255) / 256, 256>>>(in[4], in[5], in[8], in[9],
                                                    in[6], in[7], in[10], in[11], in[12]);
    init_state_kernel<<<(B_ + 255) / 256, 256>>>(xout, endp);
    init0_k<<<dim3(H_ / 64, B_ / 64), 128>>>(z, lat_W, lat_b);
    init12_k<<<dim3(TH3 / 64, 66), 128>>>(z, emb);   // zc0p (rows 0..63) + T0p (rows 64..65)

    for (int s = 1; s < MAXLEN; s++) {
        int p = s & 1;
        step1_k<<<dim3(32, B_ / 64, 2), 64>>>(p);   // layer0 (z=0) + layer1 gh (z=1)
        gi_k<<<dim3(TH3 / 48, B_ / 64), 64>>>(p);   // layer1 gi
        fuse_k<<<B_ / 8, 256>>>(p, out_b, xout, endp, s);
    }
}